// round 1
// baseline (speedup 1.0000x reference)
#include <cuda_runtime.h>

// CircularRelativePositionAttention — fused single kernel, fp32 SIMT baseline.
// B=4, H=16, S=1024, dh=64. Block = (b, h, tile of 8 query rows), 256 threads.
//
// Phases per block:
//  1. load q tile (8x64) to smem
//  2. qrb[q][dist] = q . rel_k[dist]          (513 dists)
//  3. scores[q][k] = (q.k)/8 + qrb[q][dist(q,k)]  (K staged 64-row chunks in smem)
//  4. softmax: warp-per-row (8 warps, 8 rows), unnormalized probs kept in smem
//  5. pooled[q][d] = p[(q+d)%S] + p[(q-d)%S]  (overwrites qrb buffer)
//  6. out = (p @ V + pooled @ rel_v) * (1/sum)  (V staged in same smem chunk buf)

#define S_LEN    1024
#define NHEADS   16
#define DH       64
#define QT       8          // query rows per block
#define KC       64         // K/V chunk rows
#define NTHREADS 256
#define NDIST    513
#define RBSTRIDE 516        // padded row stride for qrb/pooled (16B aligned)
#define KVSTRIDE 65         // padded row stride for K/V chunk (conflict-free dots)
#define ROWSTRIDE (NHEADS*DH)   // 1024 floats between consecutive sequence rows

#define SMEM_FLOATS (QT*DH + QT*RBSTRIDE + KC*KVSTRIDE + QT*S_LEN + 8)

__global__ __launch_bounds__(NTHREADS, 2)
void crpa_kernel(const float* __restrict__ Qg, const float* __restrict__ Kg,
                 const float* __restrict__ Vg, const float* __restrict__ RK,
                 const float* __restrict__ RV, float* __restrict__ Out)
{
    extern __shared__ float sm[];
    float* sq   = sm;                      // [QT][DH]        512
    float* srb  = sq  + QT * DH;           // [QT][RBSTRIDE]  4128  (qrb, then pooled)
    float* skv  = srb + QT * RBSTRIDE;     // [KC][KVSTRIDE]  4160  (K chunk, then V chunk)
    float* ss   = skv + KC * KVSTRIDE;     // [QT][S_LEN]     8192  (scores -> probs)
    float* sinv = ss  + QT * S_LEN;        // [QT]            8     (1/rowsum)

    const int t  = threadIdx.x;
    const int b  = blockIdx.z;
    const int h  = blockIdx.y;
    const int qb = blockIdx.x * QT;
    const size_t bh_base = (size_t)b * S_LEN * ROWSTRIDE + (size_t)h * DH;

    // ---- Phase 1: load Q tile ----
    if (t < 128) {
        int q  = t >> 4;
        int e4 = (t & 15) * 4;
        float4 v = *(const float4*)(Qg + bh_base + (size_t)(qb + q) * ROWSTRIDE + e4);
        *(float4*)(sq + q * DH + e4) = v;
    }
    __syncthreads();

    // ---- Phase 2: qrb[q][dist] = dot(q_row, rel_k[dist]) ----
    for (int dist = t; dist < NDIST; dist += NTHREADS) {
        float acc[QT];
        #pragma unroll
        for (int q = 0; q < QT; q++) acc[q] = 0.f;
        const float* rk = RK + (size_t)dist * DH;
        #pragma unroll
        for (int d = 0; d < DH; d += 4) {
            float4 r = __ldg((const float4*)(rk + d));
            #pragma unroll
            for (int q = 0; q < QT; q++) {
                float4 a = *(const float4*)(sq + q * DH + d);
                acc[q] += a.x * r.x + a.y * r.y + a.z * r.z + a.w * r.w;
            }
        }
        #pragma unroll
        for (int q = 0; q < QT; q++) srb[q * RBSTRIDE + dist] = acc[q];
    }
    __syncthreads();

    const int kq = t & 63;        // k index within chunk
    const int qh = t >> 6;        // 0..3 -> handles rows qh and qh+4
    const float scale = 0.125f;   // 1/sqrt(64)

    // ---- Phase 3: scores = QK^T * scale + bias ----
    for (int kc = 0; kc < S_LEN; kc += KC) {
        __syncthreads();   // previous chunk consumers done
        // stage K chunk [KC][DH] -> skv (padded stride)
        #pragma unroll
        for (int i = 0; i < 4; i++) {
            int f  = t + i * NTHREADS;        // float4 index 0..1023
            int kk = f >> 4;
            int d4 = (f & 15) * 4;
            float4 v = *(const float4*)(Kg + bh_base + (size_t)(kc + kk) * ROWSTRIDE + d4);
            float* dst = skv + kk * KVSTRIDE + d4;
            dst[0] = v.x; dst[1] = v.y; dst[2] = v.z; dst[3] = v.w;
        }
        __syncthreads();

        float acc0 = 0.f, acc1 = 0.f;
        #pragma unroll
        for (int d = 0; d < DH; d += 4) {
            float k0 = skv[kq * KVSTRIDE + d + 0];
            float k1 = skv[kq * KVSTRIDE + d + 1];
            float k2 = skv[kq * KVSTRIDE + d + 2];
            float k3 = skv[kq * KVSTRIDE + d + 3];
            float4 a0 = *(const float4*)(sq + qh * DH + d);
            float4 a1 = *(const float4*)(sq + (qh + 4) * DH + d);
            acc0 += a0.x * k0 + a0.y * k1 + a0.z * k2 + a0.w * k3;
            acc1 += a1.x * k0 + a1.y * k1 + a1.z * k2 + a1.w * k3;
        }
        const int kg  = kc + kq;
        const int qg0 = qb + qh;
        const int qg1 = qb + qh + 4;
        int d0 = (qg0 - kg) & (S_LEN - 1); int dist0 = min(d0, S_LEN - d0);
        int d1 = (qg1 - kg) & (S_LEN - 1); int dist1 = min(d1, S_LEN - d1);
        ss[qh * S_LEN + kg]       = acc0 * scale + srb[qh * RBSTRIDE + dist0];
        ss[(qh + 4) * S_LEN + kg] = acc1 * scale + srb[(qh + 4) * RBSTRIDE + dist1];
    }
    __syncthreads();

    // ---- Phase 4: softmax, warp per row (unnormalized; keep 1/sum) ----
    {
        const int w    = t >> 5;
        const int lane = t & 31;
        float* row = ss + w * S_LEN;
        float m = -1e30f;
        for (int k = lane; k < S_LEN; k += 32) m = fmaxf(m, row[k]);
        #pragma unroll
        for (int o = 16; o; o >>= 1) m = fmaxf(m, __shfl_xor_sync(0xFFFFFFFFu, m, o));
        float sum = 0.f;
        for (int k = lane; k < S_LEN; k += 32) {
            float p = __expf(row[k] - m);
            row[k] = p;
            sum += p;
        }
        #pragma unroll
        for (int o = 16; o; o >>= 1) sum += __shfl_xor_sync(0xFFFFFFFFu, sum, o);
        if (lane == 0) sinv[w] = 1.f / sum;
    }
    __syncthreads();

    // ---- Phase 5: pooled[q][dd] (overwrite srb) ----
    for (int dd = t; dd < NDIST; dd += NTHREADS) {
        #pragma unroll
        for (int q = 0; q < QT; q++) {
            int qg = qb + q;
            int k1 = (qg + dd) & (S_LEN - 1);
            float v = ss[q * S_LEN + k1];
            if (dd != 0 && dd != 512) {
                int k2 = (qg - dd) & (S_LEN - 1);
                v += ss[q * S_LEN + k2];
            }
            srb[q * RBSTRIDE + dd] = v;
        }
    }
    __syncthreads();

    // ---- Phase 6a: out = p @ V (V staged chunkwise in skv) ----
    const int e = t & 63;
    float acc0 = 0.f, acc1 = 0.f;
    for (int kc = 0; kc < S_LEN; kc += KC) {
        __syncthreads();
        #pragma unroll
        for (int i = 0; i < 4; i++) {
            int f  = t + i * NTHREADS;
            int kk = f >> 4;
            int d4 = (f & 15) * 4;
            float4 v = *(const float4*)(Vg + bh_base + (size_t)(kc + kk) * ROWSTRIDE + d4);
            float* dst = skv + kk * KVSTRIDE + d4;
            dst[0] = v.x; dst[1] = v.y; dst[2] = v.z; dst[3] = v.w;
        }
        __syncthreads();
        #pragma unroll
        for (int kk = 0; kk < KC; kk += 4) {
            float4 p0 = *(const float4*)(ss + qh * S_LEN + kc + kk);
            float4 p1 = *(const float4*)(ss + (qh + 4) * S_LEN + kc + kk);
            float v0 = skv[(kk + 0) * KVSTRIDE + e];
            float v1 = skv[(kk + 1) * KVSTRIDE + e];
            float v2 = skv[(kk + 2) * KVSTRIDE + e];
            float v3 = skv[(kk + 3) * KVSTRIDE + e];
            acc0 += p0.x * v0 + p0.y * v1 + p0.z * v2 + p0.w * v3;
            acc1 += p1.x * v0 + p1.y * v1 + p1.z * v2 + p1.w * v3;
        }
    }

    // ---- Phase 6b: out += pooled @ rel_v ----
    #pragma unroll 4
    for (int dd = 0; dd < 512; dd += 4) {
        float4 p0 = *(const float4*)(srb + qh * RBSTRIDE + dd);
        float4 p1 = *(const float4*)(srb + (qh + 4) * RBSTRIDE + dd);
        float r0 = __ldg(RV + (size_t)(dd + 0) * DH + e);
        float r1 = __ldg(RV + (size_t)(dd + 1) * DH + e);
        float r2 = __ldg(RV + (size_t)(dd + 2) * DH + e);
        float r3 = __ldg(RV + (size_t)(dd + 3) * DH + e);
        acc0 += p0.x * r0 + p0.y * r1 + p0.z * r2 + p0.w * r3;
        acc1 += p1.x * r0 + p1.y * r1 + p1.z * r2 + p1.w * r3;
    }
    {
        float r = __ldg(RV + (size_t)512 * DH + e);
        acc0 += srb[qh * RBSTRIDE + 512] * r;
        acc1 += srb[(qh + 4) * RBSTRIDE + 512] * r;
    }

    // ---- write (normalize) ----
    float o0 = acc0 * sinv[qh];
    float o1 = acc1 * sinv[qh + 4];
    Out[bh_base + (size_t)(qb + qh) * ROWSTRIDE + e]     = o0;
    Out[bh_base + (size_t)(qb + qh + 4) * ROWSTRIDE + e] = o1;
}

extern "C" void kernel_launch(void* const* d_in, const int* in_sizes, int n_in,
                              void* d_out, int out_size)
{
    const float* Q  = (const float*)d_in[0];
    const float* K  = (const float*)d_in[1];
    const float* V  = (const float*)d_in[2];
    const float* RK = (const float*)d_in[3];
    const float* RV = (const float*)d_in[4];
    float* Out = (float*)d_out;

    const int B = in_sizes[0] / (S_LEN * ROWSTRIDE);  // 4

    const int smem_bytes = SMEM_FLOATS * (int)sizeof(float);
    cudaFuncSetAttribute(crpa_kernel, cudaFuncAttributeMaxDynamicSharedMemorySize, smem_bytes);

    dim3 grid(S_LEN / QT, NHEADS, B);
    crpa_kernel<<<grid, NTHREADS, smem_bytes>>>(Q, K, V, RK, RV, Out);
}

// round 2
// speedup vs baseline: 1.4407x; 1.4407x over previous
#include <cuda_runtime.h>

// CircularRelativePositionAttention — fused fp32 SIMT, round 2.
// B=4, H=16, S=1024, dh=64. Block = (b, h, 8 query rows), 256 threads, 2 blocks/SM.
//
// Key ideas vs round 1:
//  - every GEMM-ish phase: warp-uniform broadcast loads for the "small" operand
//    (q rows / prob rows), conflict-free LDS.128 (stride 68) or conflict-free
//    scalar LDS for the "big" operand, >=4 accumulators per thread.
//  - rel_k staged through smem chunks (coalesced LDG) instead of scattered LDG.
//  - phase 6: 4-way k/dist split per output, accumulate p@V and pooled@rel_v in
//    the same registers, single smem reduction at the end.

#define S_LEN    1024
#define NHEADS   16
#define DH       64
#define QT       8
#define KC       128         // K/V/rel_k chunk rows staged in smem
#define NTHREADS 256
#define NDIST    513
#define RBSTRIDE 516         // qrb/pooled row stride (16B aligned)
#define KVSTRIDE 68          // chunk row stride: float4-aligned, conflict-free
#define ROWSTRIDE (NHEADS*DH)

#define SQ_F   (QT*DH)            // 512
#define SRB_F  (QT*RBSTRIDE)      // 4128
#define SKV_F  (KC*KVSTRIDE)      // 8704
#define SS_F   (QT*S_LEN)         // 8192
#define SMEM_FLOATS (SQ_F + SRB_F + SKV_F + SS_F + 8)

__global__ __launch_bounds__(NTHREADS, 2)
void crpa_kernel(const float* __restrict__ Qg, const float* __restrict__ Kg,
                 const float* __restrict__ Vg, const float* __restrict__ RK,
                 const float* __restrict__ RV, float* __restrict__ Out)
{
    extern __shared__ float sm[];
    float* sq   = sm;                  // [QT][DH]
    float* srb  = sq  + SQ_F;          // [QT][RBSTRIDE]  qrb -> pooled
    float* skv  = srb + SRB_F;         // [KC][KVSTRIDE]  relk/K/V chunk -> reduction buf
    float* ss   = skv + SKV_F;         // [QT][S_LEN]     scores -> probs
    float* sinv = ss  + SS_F;          // [QT]

    const int t  = threadIdx.x;
    const int b  = blockIdx.z;
    const int h  = blockIdx.y;
    const int qb = blockIdx.x * QT;
    const size_t bh_base = (size_t)b * S_LEN * ROWSTRIDE + (size_t)h * DH;

    // ---- Phase 1: load Q tile ----
    if (t < 128) {
        int q  = t >> 4;
        int e4 = (t & 15) * 4;
        float4 v = *(const float4*)(Qg + bh_base + (size_t)(qb + q) * ROWSTRIDE + e4);
        *(float4*)(sq + q * DH + e4) = v;
    }

    const int kq = t & 127;           // row within chunk
    const int q0 = (t >> 7) * 4;      // 0 or 4: this thread's 4 q rows

    // ---- Phase 2: qrb[q][dist] = q . rel_k[dist], dist in [0,512) chunked ----
    for (int dc = 0; dc < 512; dc += KC) {
        __syncthreads();
        #pragma unroll
        for (int i = 0; i < 8; i++) {
            int f  = t + i * NTHREADS;          // float4 idx 0..2047
            int kk = f >> 4;
            int d4 = (f & 15) * 4;
            float4 v = *(const float4*)(RK + (size_t)(dc + kk) * DH + d4);
            *(float4*)(skv + kk * KVSTRIDE + d4) = v;
        }
        __syncthreads();

        float acc[4] = {0.f, 0.f, 0.f, 0.f};
        #pragma unroll
        for (int d = 0; d < DH; d += 4) {
            float4 r = *(const float4*)(skv + kq * KVSTRIDE + d);
            #pragma unroll
            for (int j = 0; j < 4; j++) {
                float4 a = *(const float4*)(sq + (q0 + j) * DH + d);
                acc[j] += a.x * r.x + a.y * r.y + a.z * r.z + a.w * r.w;
            }
        }
        #pragma unroll
        for (int j = 0; j < 4; j++)
            srb[(q0 + j) * RBSTRIDE + dc + kq] = acc[j];
    }
    // dist == 512 leftover: 128 threads, 16 lanes per q row
    if (t < 128) {
        int q  = t >> 4;
        int d4 = (t & 15) * 4;
        const float* rk = RK + (size_t)512 * DH + d4;
        const float* a  = sq + q * DH + d4;
        float p = a[0]*rk[0] + a[1]*rk[1] + a[2]*rk[2] + a[3]*rk[3];
        #pragma unroll
        for (int o = 8; o; o >>= 1) p += __shfl_down_sync(0xFFFFFFFFu, p, o, 16);
        if ((t & 15) == 0) srb[q * RBSTRIDE + 512] = p;
    }

    const float scale = 0.125f;       // 1/sqrt(64)

    // ---- Phase 3: scores = QK^T*scale + bias ----
    for (int kc = 0; kc < S_LEN; kc += KC) {
        __syncthreads();
        #pragma unroll
        for (int i = 0; i < 8; i++) {
            int f  = t + i * NTHREADS;
            int kk = f >> 4;
            int d4 = (f & 15) * 4;
            float4 v = *(const float4*)(Kg + bh_base + (size_t)(kc + kk) * ROWSTRIDE + d4);
            *(float4*)(skv + kk * KVSTRIDE + d4) = v;
        }
        __syncthreads();

        float acc[4] = {0.f, 0.f, 0.f, 0.f};
        #pragma unroll
        for (int d = 0; d < DH; d += 4) {
            float4 r = *(const float4*)(skv + kq * KVSTRIDE + d);
            #pragma unroll
            for (int j = 0; j < 4; j++) {
                float4 a = *(const float4*)(sq + (q0 + j) * DH + d);
                acc[j] += a.x * r.x + a.y * r.y + a.z * r.z + a.w * r.w;
            }
        }
        const int kg = kc + kq;
        #pragma unroll
        for (int j = 0; j < 4; j++) {
            int qg = qb + q0 + j;
            int dd = (qg - kg) & (S_LEN - 1);
            int dist = min(dd, S_LEN - dd);
            ss[(q0 + j) * S_LEN + kg] = acc[j] * scale + srb[(q0 + j) * RBSTRIDE + dist];
        }
    }
    __syncthreads();

    // ---- Phase 4: softmax, warp per row (unnormalized; keep 1/sum) ----
    {
        const int w    = t >> 5;
        const int lane = t & 31;
        float* row = ss + w * S_LEN;
        float m = -1e30f;
        for (int k = lane; k < S_LEN; k += 32) m = fmaxf(m, row[k]);
        #pragma unroll
        for (int o = 16; o; o >>= 1) m = fmaxf(m, __shfl_xor_sync(0xFFFFFFFFu, m, o));
        float sum = 0.f;
        for (int k = lane; k < S_LEN; k += 32) {
            float p = __expf(row[k] - m);
            row[k] = p;
            sum += p;
        }
        #pragma unroll
        for (int o = 16; o; o >>= 1) sum += __shfl_xor_sync(0xFFFFFFFFu, sum, o);
        if (lane == 0) sinv[w] = 1.f / sum;
    }
    __syncthreads();

    // ---- Phase 5: pooled[q][dd] = p[(q+dd)%S] (+ p[(q-dd)%S]) -> srb ----
    for (int dd = t; dd < NDIST; dd += NTHREADS) {
        #pragma unroll
        for (int q = 0; q < QT; q++) {
            int qg = qb + q;
            int k1 = (qg + dd) & (S_LEN - 1);
            float v = ss[q * S_LEN + k1];
            if (dd != 0 && dd != 512) {
                int k2 = (qg - dd) & (S_LEN - 1);
                v += ss[q * S_LEN + k2];
            }
            srb[q * RBSTRIDE + dd] = v;
        }
    }

    // ---- Phase 6: out = p @ V + pooled @ rel_v ----
    const int e = t & 63;             // output dim
    const int g = t >> 6;             // quarter (k-range / dist-range)
    float acc[QT];
    #pragma unroll
    for (int q = 0; q < QT; q++) acc[q] = 0.f;

    // 6a: p @ V, V chunked in smem, each thread covers 32 of 128 k per chunk
    for (int kc = 0; kc < S_LEN; kc += KC) {
        __syncthreads();
        #pragma unroll
        for (int i = 0; i < 8; i++) {
            int f  = t + i * NTHREADS;
            int kk = f >> 4;
            int d4 = (f & 15) * 4;
            float4 v = *(const float4*)(Vg + bh_base + (size_t)(kc + kk) * ROWSTRIDE + d4);
            *(float4*)(skv + kk * KVSTRIDE + d4) = v;
        }
        __syncthreads();

        const int kl = g * 32;
        #pragma unroll
        for (int kk = 0; kk < 32; kk += 4) {
            float v0 = skv[(kl + kk + 0) * KVSTRIDE + e];
            float v1 = skv[(kl + kk + 1) * KVSTRIDE + e];
            float v2 = skv[(kl + kk + 2) * KVSTRIDE + e];
            float v3 = skv[(kl + kk + 3) * KVSTRIDE + e];
            #pragma unroll
            for (int q = 0; q < QT; q++) {
                float4 p = *(const float4*)(ss + q * S_LEN + kc + kl + kk);
                acc[q] += p.x * v0 + p.y * v1 + p.z * v2 + p.w * v3;
            }
        }
    }

    // 6b: pooled @ rel_v, dist quarter per thread
    {
        const float* RVe = RV + e;
        const int dbase = g * 128;
        #pragma unroll 2
        for (int dd = 0; dd < 128; dd += 4) {
            int d0 = dbase + dd;
            float r0 = __ldg(RVe + (size_t)(d0 + 0) * DH);
            float r1 = __ldg(RVe + (size_t)(d0 + 1) * DH);
            float r2 = __ldg(RVe + (size_t)(d0 + 2) * DH);
            float r3 = __ldg(RVe + (size_t)(d0 + 3) * DH);
            #pragma unroll
            for (int q = 0; q < QT; q++) {
                float4 p = *(const float4*)(srb + q * RBSTRIDE + d0);
                acc[q] += p.x * r0 + p.y * r1 + p.z * r2 + p.w * r3;
            }
        }
        if (g == 0) {
            float r = __ldg(RVe + (size_t)512 * DH);
            #pragma unroll
            for (int q = 0; q < QT; q++)
                acc[q] += srb[q * RBSTRIDE + 512] * r;
        }
    }

    // reduction across the 4 quarters (reuse skv)
    __syncthreads();
    #pragma unroll
    for (int q = 0; q < QT; q++)
        skv[(q * 4 + g) * 64 + e] = acc[q];
    __syncthreads();
    #pragma unroll
    for (int i = 0; i < 2; i++) {
        int o  = t + i * NTHREADS;     // 0..511
        int q  = o >> 6;
        int ee = o & 63;
        float r = skv[(q * 4 + 0) * 64 + ee] + skv[(q * 4 + 1) * 64 + ee]
                + skv[(q * 4 + 2) * 64 + ee] + skv[(q * 4 + 3) * 64 + ee];
        Out[bh_base + (size_t)(qb + q) * ROWSTRIDE + ee] = r * sinv[q];
    }
}

extern "C" void kernel_launch(void* const* d_in, const int* in_sizes, int n_in,
                              void* d_out, int out_size)
{
    const float* Q  = (const float*)d_in[0];
    const float* K  = (const float*)d_in[1];
    const float* V  = (const float*)d_in[2];
    const float* RK = (const float*)d_in[3];
    const float* RV = (const float*)d_in[4];
    float* Out = (float*)d_out;

    const int B = in_sizes[0] / (S_LEN * ROWSTRIDE);

    const int smem_bytes = SMEM_FLOATS * (int)sizeof(float);
    cudaFuncSetAttribute(crpa_kernel, cudaFuncAttributeMaxDynamicSharedMemorySize, smem_bytes);

    dim3 grid(S_LEN / QT, NHEADS, B);
    crpa_kernel<<<grid, NTHREADS, smem_bytes>>>(Q, K, V, RK, RV, Out);
}

// round 4
// speedup vs baseline: 2.4167x; 1.6775x over previous
#include <cuda_runtime.h>
#include <cuda_bf16.h>
#include <cstdint>

// CircularRelativePositionAttention — legacy tensor core (mma.sync bf16, hi/lo split).
// B=4,H=16 -> 64 head-batches; S=1024; dh=64.
//
// Pipeline:
//  k_split : Q (x1), K (x1/8)  -> bf16 interleaved [bh][s][128] (hi 0-63 | lo 64-127)
//  k_vt    : V -> transposed    [bh][e 64][2048]   (hi s 0-1023 | lo 1024-2047)
//  k_rel   : rel_k -> [640][128] (rows>=513 zero); rel_v -> [64][1280] transposed
//  k_bias  : G[bh][q][640] = Q . rel_k^T  (fp32)
//  k_scores: per (bh, 32 q-rows): scores = QK^T + gather(G)  (rows in smem),
//            softmax -> P bf16 hi/lo gmem, pooled bf16 hi/lo gmem, 1/sum
//  k_out   : Out = (P @ V^T + pooled @ rel_v^T) * (1/sum)

#define BHN 64
#define SL  1024
#define NDP 640                 // padded distance dim (513 used)

// ---------------- scratch ----------------
__device__ __nv_bfloat16 g_Q [(size_t)BHN*SL*128];
__device__ __nv_bfloat16 g_K [(size_t)BHN*SL*128];
__device__ __nv_bfloat16 g_Vt[(size_t)BHN*64*2048];
__device__ __nv_bfloat16 g_RK[(size_t)NDP*128];
__device__ __nv_bfloat16 g_RVt[(size_t)64*1280];
__device__ float         g_G [(size_t)BHN*SL*NDP];
__device__ __nv_bfloat16 g_P [(size_t)BHN*SL*2048];
__device__ __nv_bfloat16 g_PL[(size_t)BHN*SL*1280];
__device__ float         g_sinv[BHN*SL];

// ---------------- helpers ----------------
__device__ __forceinline__ uint32_t smem_u32(const void* p) {
    uint32_t a;
    asm("{ .reg .u64 t; cvta.to.shared.u64 t, %1; cvt.u32.u64 %0, t; }" : "=r"(a) : "l"(p));
    return a;
}
__device__ __forceinline__ void ldsm4(uint32_t& r0, uint32_t& r1, uint32_t& r2, uint32_t& r3, uint32_t a) {
    asm volatile("ldmatrix.sync.aligned.m8n8.x4.shared.b16 {%0,%1,%2,%3}, [%4];"
                 : "=r"(r0), "=r"(r1), "=r"(r2), "=r"(r3) : "r"(a));
}
__device__ __forceinline__ void mma16816(float* c, uint32_t a0, uint32_t a1, uint32_t a2, uint32_t a3,
                                         uint32_t b0, uint32_t b1) {
    asm volatile("mma.sync.aligned.m16n8k16.row.col.f32.bf16.bf16.f32 "
                 "{%0,%1,%2,%3}, {%4,%5,%6,%7}, {%8,%9}, {%0,%1,%2,%3};"
                 : "+f"(c[0]), "+f"(c[1]), "+f"(c[2]), "+f"(c[3])
                 : "r"(a0), "r"(a1), "r"(a2), "r"(a3), "r"(b0), "r"(b1));
}
__device__ __forceinline__ void split_bf(float x, __nv_bfloat16& h, __nv_bfloat16& l) {
    h = __float2bfloat16(x);
    l = __float2bfloat16(x - __bfloat162float(h));
}
__device__ __forceinline__ uint32_t pack2(__nv_bfloat16 a, __nv_bfloat16 b) {
    __nv_bfloat162 t = {a, b};
    return *(uint32_t*)&t;
}

// ---------------- prep: split Q/K ----------------
__global__ void k_split(const float* __restrict__ src, __nv_bfloat16* __restrict__ dst, float scale)
{
    int i4 = blockIdx.x * 256 + threadIdx.x;       // over BHN*SL*64/4
    int e4 = (i4 & 15) * 4;
    int s  = (i4 >> 4) & 1023;
    int bh = i4 >> 14;
    int b = bh >> 4, h = bh & 15;
    float4 v = *(const float4*)(src + ((size_t)(b * 1024) + s) * 1024 + h * 64 + e4);
    __nv_bfloat16 h0,l0,h1,l1,h2,l2,h3,l3;
    split_bf(v.x*scale,h0,l0); split_bf(v.y*scale,h1,l1);
    split_bf(v.z*scale,h2,l2); split_bf(v.w*scale,h3,l3);
    __nv_bfloat16* d = dst + ((size_t)bh * 1024 + s) * 128;
    *(uint2*)(d + e4)      = make_uint2(pack2(h0,h1), pack2(h2,h3));
    *(uint2*)(d + 64 + e4) = make_uint2(pack2(l0,l1), pack2(l2,l3));
}

// ---------------- prep: V transpose ----------------
__global__ void k_vt(const float* __restrict__ V)
{
    extern __shared__ float sv[];    // [256][65]
    int tid = threadIdx.x, sc = blockIdx.x, bh = blockIdx.y;
    int b = bh >> 4, h = bh & 15;
    for (int i = tid; i < 4096; i += 256) {
        int s = i >> 4, e4 = (i & 15) * 4;
        float4 v = *(const float4*)(V + ((size_t)(b * 1024) + sc * 256 + s) * 1024 + h * 64 + e4);
        float* d = sv + s * 65 + e4;
        d[0]=v.x; d[1]=v.y; d[2]=v.z; d[3]=v.w;
    }
    __syncthreads();
    for (int i = tid; i < 4096; i += 256) {
        int e = i >> 6, s4 = (i & 63) * 4;
        __nv_bfloat16 hh[4], ll[4];
        #pragma unroll
        for (int j = 0; j < 4; j++) split_bf(sv[(s4 + j) * 65 + e], hh[j], ll[j]);
        size_t di = ((size_t)bh * 64 + e) * 2048 + sc * 256 + s4;
        *(uint2*)(g_Vt + di)        = make_uint2(pack2(hh[0],hh[1]), pack2(hh[2],hh[3]));
        *(uint2*)(g_Vt + di + 1024) = make_uint2(pack2(ll[0],ll[1]), pack2(ll[2],ll[3]));
    }
}

// ---------------- prep: rel tables ----------------
__global__ void k_rel(const float* __restrict__ RK, const float* __restrict__ RV)
{
    int r = blockIdx.x;      // 0..639
    int e = threadIdx.x;     // 0..63
    float fk = 0.f, fv = 0.f;
    if (r < 513) { fk = RK[(size_t)r * 64 + e]; fv = RV[(size_t)r * 64 + e]; }
    __nv_bfloat16 h, l;
    split_bf(fk, h, l);
    g_RK[(size_t)r * 128 + e] = h;  g_RK[(size_t)r * 128 + 64 + e] = l;
    split_bf(fv, h, l);
    g_RVt[(size_t)e * 1280 + r] = h;  g_RVt[(size_t)e * 1280 + 640 + r] = l;
}

// ---------------- K1: G = Q . RK^T ----------------
#define TS1 136
#define K1_SMEM (2*128*TS1*2)
__global__ __launch_bounds__(256) void k_bias()
{
    extern __shared__ char smc[];
    __nv_bfloat16* smA = (__nv_bfloat16*)smc;
    __nv_bfloat16* smB = smA + 128 * TS1;
    int tid = threadIdx.x, lane = tid & 31, wid = tid >> 5;
    int qt = blockIdx.x, bh = blockIdx.y;
    int wm = wid & 1, wn = wid >> 1;

    const __nv_bfloat16* Ag = g_Q + ((size_t)bh * 1024 + qt * 128) * 128;
    for (int i = tid; i < 2048; i += 256) {
        int r = i >> 4, c = (i & 15) * 8;
        *(uint4*)(smA + r * TS1 + c) = *(const uint4*)(Ag + r * 128 + c);
    }
    uint32_t aAddr = smem_u32(smA) + (uint32_t)(((wm * 64 + (lane & 15)) * TS1 + ((lane >> 4) << 3)) * 2);
    uint32_t bAddr = smem_u32(smB) + (uint32_t)(((wn * 32 + (lane & 7) + ((lane >> 4) << 3)) * TS1 + ((lane & 8) ? 8 : 0)) * 2);

    for (int nc = 0; nc < 5; nc++) {
        __syncthreads();
        const __nv_bfloat16* Bg = g_RK + (size_t)nc * 128 * 128;
        for (int i = tid; i < 2048; i += 256) {
            int r = i >> 4, c = (i & 15) * 8;
            *(uint4*)(smB + r * TS1 + c) = *(const uint4*)(Bg + r * 128 + c);
        }
        __syncthreads();

        float acc[4][4][4];
        #pragma unroll
        for (int m = 0; m < 4; m++) for (int n = 0; n < 4; n++) for (int i = 0; i < 4; i++) acc[m][n][i] = 0.f;

        #pragma unroll
        for (int p = 0; p < 3; p++) {
            int ka = (p == 1) ? 64 : 0, kb = (p == 2) ? 64 : 0;
            #pragma unroll
            for (int ks = 0; ks < 4; ks++) {
                uint32_t ao = (uint32_t)((ka + ks * 16) * 2), bo = (uint32_t)((kb + ks * 16) * 2);
                uint32_t b0,b1,b2,b3,b4,b5,b6,b7;
                ldsm4(b0,b1,b2,b3, bAddr + bo);
                ldsm4(b4,b5,b6,b7, bAddr + 16 * TS1 * 2 + bo);
                #pragma unroll
                for (int mt = 0; mt < 4; mt++) {
                    uint32_t a0,a1,a2,a3;
                    ldsm4(a0,a1,a2,a3, aAddr + mt * 16 * TS1 * 2 + ao);
                    mma16816(acc[mt][0], a0,a1,a2,a3, b0,b1);
                    mma16816(acc[mt][1], a0,a1,a2,a3, b2,b3);
                    mma16816(acc[mt][2], a0,a1,a2,a3, b4,b5);
                    mma16816(acc[mt][3], a0,a1,a2,a3, b6,b7);
                }
            }
        }
        // write G
        #pragma unroll
        for (int mt = 0; mt < 4; mt++) {
            int row = wm * 64 + mt * 16 + (lane >> 2);
            float* G0 = g_G + ((size_t)bh * 1024 + qt * 128 + row) * NDP + nc * 128 + wn * 32 + (lane & 3) * 2;
            #pragma unroll
            for (int nt = 0; nt < 4; nt++) {
                *(float2*)(G0 + nt * 8)            = make_float2(acc[mt][nt][0], acc[mt][nt][1]);
                *(float2*)(G0 + 8 * NDP + nt * 8)  = make_float2(acc[mt][nt][2], acc[mt][nt][3]);
            }
        }
    }
}

// ---------------- K2: scores + softmax + P + pooled ----------------
#define K2_SMEM (32*TS1*2 + 128*TS1*2 + 32*1024*4)
__global__ __launch_bounds__(256) void k_scores()
{
    extern __shared__ char smc[];
    __nv_bfloat16* smA = (__nv_bfloat16*)smc;                 // [32][136]
    __nv_bfloat16* smB = smA + 32 * TS1;                      // [128][136]
    float* smS = (float*)(smc + 160 * TS1 * 2);               // [32][1024]
    int tid = threadIdx.x, lane = tid & 31, wid = tid >> 5;
    int qt = blockIdx.x, bh = blockIdx.y;
    int wm = wid & 1, wn = wid >> 1;
    const int q0 = qt * 32;

    const __nv_bfloat16* Ag = g_Q + ((size_t)bh * 1024 + q0) * 128;
    for (int i = tid; i < 512; i += 256) {
        int r = i >> 4, c = (i & 15) * 8;
        *(uint4*)(smA + r * TS1 + c) = *(const uint4*)(Ag + r * 128 + c);
    }
    uint32_t aAddr = smem_u32(smA) + (uint32_t)(((wm * 16 + (lane & 15)) * TS1 + ((lane >> 4) << 3)) * 2);
    uint32_t bAddr = smem_u32(smB) + (uint32_t)(((wn * 32 + (lane & 7) + ((lane >> 4) << 3)) * TS1 + ((lane & 8) ? 8 : 0)) * 2);
    const float* Grow = g_G + ((size_t)bh * 1024 + q0) * NDP;

    for (int kc = 0; kc < 8; kc++) {
        __syncthreads();
        const __nv_bfloat16* Bg = g_K + ((size_t)bh * 1024 + kc * 128) * 128;
        for (int i = tid; i < 2048; i += 256) {
            int r = i >> 4, c = (i & 15) * 8;
            *(uint4*)(smB + r * TS1 + c) = *(const uint4*)(Bg + r * 128 + c);
        }
        __syncthreads();

        float acc[4][4];
        #pragma unroll
        for (int n = 0; n < 4; n++) for (int i = 0; i < 4; i++) acc[n][i] = 0.f;

        #pragma unroll
        for (int p = 0; p < 3; p++) {
            int ka = (p == 1) ? 64 : 0, kb = (p == 2) ? 64 : 0;
            #pragma unroll
            for (int ks = 0; ks < 4; ks++) {
                uint32_t ao = (uint32_t)((ka + ks * 16) * 2), bo = (uint32_t)((kb + ks * 16) * 2);
                uint32_t b0,b1,b2,b3,b4,b5,b6,b7, a0,a1,a2,a3;
                ldsm4(b0,b1,b2,b3, bAddr + bo);
                ldsm4(b4,b5,b6,b7, bAddr + 16 * TS1 * 2 + bo);
                ldsm4(a0,a1,a2,a3, aAddr + ao);
                mma16816(acc[0], a0,a1,a2,a3, b0,b1);
                mma16816(acc[1], a0,a1,a2,a3, b2,b3);
                mma16816(acc[2], a0,a1,a2,a3, b4,b5);
                mma16816(acc[3], a0,a1,a2,a3, b6,b7);
            }
        }
        // epilogue: add bias gather, store scores to smem
        int r0 = wm * 16 + (lane >> 2);
        int qg0 = q0 + r0, qg1 = qg0 + 8;
        #pragma unroll
        for (int nt = 0; nt < 4; nt++) {
            int kg = kc * 128 + wn * 32 + nt * 8 + (lane & 3) * 2;
            int dA0 = (qg0 - kg) & 1023;       dA0 = min(dA0, 1024 - dA0);
            int dA1 = (qg0 - kg - 1) & 1023;   dA1 = min(dA1, 1024 - dA1);
            int dB0 = (qg1 - kg) & 1023;       dB0 = min(dB0, 1024 - dB0);
            int dB1 = (qg1 - kg - 1) & 1023;   dB1 = min(dB1, 1024 - dB1);
            smS[r0 * 1024 + kg]           = acc[nt][0] + __ldg(Grow + (size_t)r0 * NDP + dA0);
            smS[r0 * 1024 + kg + 1]       = acc[nt][1] + __ldg(Grow + (size_t)r0 * NDP + dA1);
            smS[(r0 + 8) * 1024 + kg]     = acc[nt][2] + __ldg(Grow + (size_t)(r0 + 8) * NDP + dB0);
            smS[(r0 + 8) * 1024 + kg + 1] = acc[nt][3] + __ldg(Grow + (size_t)(r0 + 8) * NDP + dB1);
        }
    }
    __syncthreads();

    // softmax + P store + pooled, warp per row (4 rows each)
    for (int it = 0; it < 4; it++) {
        int r = it * 8 + wid;
        int qg = q0 + r;
        float* row = smS + r * 1024;
        float4 f[8];
        float m = -1e30f;
        #pragma unroll
        for (int j = 0; j < 8; j++) {
            f[j] = ((float4*)row)[lane + j * 32];
            m = fmaxf(m, fmaxf(fmaxf(f[j].x, f[j].y), fmaxf(f[j].z, f[j].w)));
        }
        #pragma unroll
        for (int o = 16; o; o >>= 1) m = fmaxf(m, __shfl_xor_sync(0xFFFFFFFFu, m, o));
        float sum = 0.f;
        __nv_bfloat16* Pr = g_P + ((size_t)bh * 1024 + qg) * 2048;
        #pragma unroll
        for (int j = 0; j < 8; j++) {
            float p0 = __expf(f[j].x - m), p1 = __expf(f[j].y - m);
            float p2 = __expf(f[j].z - m), p3 = __expf(f[j].w - m);
            sum += (p0 + p1) + (p2 + p3);
            ((float4*)row)[lane + j * 32] = make_float4(p0, p1, p2, p3);
            __nv_bfloat16 h0,l0,h1,l1,h2,l2,h3,l3;
            split_bf(p0,h0,l0); split_bf(p1,h1,l1); split_bf(p2,h2,l2); split_bf(p3,h3,l3);
            int k4 = (lane + j * 32) * 4;
            *(uint2*)(Pr + k4)        = make_uint2(pack2(h0,h1), pack2(h2,h3));
            *(uint2*)(Pr + 1024 + k4) = make_uint2(pack2(l0,l1), pack2(l2,l3));
        }
        #pragma unroll
        for (int o = 16; o; o >>= 1) sum += __shfl_xor_sync(0xFFFFFFFFu, sum, o);
        if (lane == 0) g_sinv[bh * 1024 + qg] = 1.f / sum;
        __syncwarp();
        __nv_bfloat16* PLr = g_PL + ((size_t)bh * 1024 + qg) * 1280;
        for (int dd = lane; dd < 640; dd += 32) {
            float v = 0.f;
            if (dd <= 512) {
                v = row[(qg + dd) & 1023];
                if (dd != 0 && dd != 512) v += row[(qg - dd) & 1023];
            }
            __nv_bfloat16 h, l;
            split_bf(v, h, l);
            PLr[dd] = h;  PLr[640 + dd] = l;
        }
    }
}

// ---------------- K4: Out = (P@V^T + PL@RV^T) * sinv ----------------
#define TS4 264
#define K4_SMEM ((128+64)*TS4*2)
__global__ __launch_bounds__(256) void k_out(float* __restrict__ Out)
{
    extern __shared__ char smc[];
    __nv_bfloat16* smA = (__nv_bfloat16*)smc;        // [128][264]  hi 0-127 | lo 128-255
    __nv_bfloat16* smB = smA + 128 * TS4;            // [64][264]
    int tid = threadIdx.x, lane = tid & 31, wid = tid >> 5;
    int qt = blockIdx.x, bh = blockIdx.y;
    int wm = wid & 1, wn = wid >> 1;

    float acc[4][2][4];
    #pragma unroll
    for (int m = 0; m < 4; m++) for (int n = 0; n < 2; n++) for (int i = 0; i < 4; i++) acc[m][n][i] = 0.f;

    uint32_t aAddr = smem_u32(smA) + (uint32_t)(((wm * 64 + (lane & 15)) * TS4 + ((lane >> 4) << 3)) * 2);
    uint32_t bAddr = smem_u32(smB) + (uint32_t)(((wn * 16 + (lane & 7) + ((lane >> 4) << 3)) * TS4 + ((lane & 8) ? 8 : 0)) * 2);

    for (int ch = 0; ch < 13; ch++) {
        __syncthreads();
        const __nv_bfloat16 *Ag, *Bg;
        int hiOff, loOff, astr, bstr;
        if (ch < 8) {
            Ag = g_P  + ((size_t)bh * 1024 + qt * 128) * 2048;  astr = 2048;
            Bg = g_Vt + (size_t)bh * 64 * 2048;                 bstr = 2048;
            hiOff = ch * 128;  loOff = 1024 + ch * 128;
        } else {
            Ag = g_PL + ((size_t)bh * 1024 + qt * 128) * 1280;  astr = 1280;
            Bg = g_RVt;                                         bstr = 1280;
            hiOff = (ch - 8) * 128;  loOff = 640 + (ch - 8) * 128;
        }
        for (int i = tid; i < 128 * 32; i += 256) {
            int r = i >> 5, c = i & 31;
            int src = (c < 16) ? (hiOff + c * 8) : (loOff + (c - 16) * 8);
            *(uint4*)(smA + r * TS4 + c * 8) = *(const uint4*)(Ag + (size_t)r * astr + src);
        }
        for (int i = tid; i < 64 * 32; i += 256) {
            int r = i >> 5, c = i & 31;
            int src = (c < 16) ? (hiOff + c * 8) : (loOff + (c - 16) * 8);
            *(uint4*)(smB + r * TS4 + c * 8) = *(const uint4*)(Bg + (size_t)r * bstr + src);
        }
        __syncthreads();

        #pragma unroll
        for (int p = 0; p < 3; p++) {
            int ka = (p == 1) ? 128 : 0, kb = (p == 2) ? 128 : 0;
            #pragma unroll
            for (int ks = 0; ks < 8; ks++) {
                uint32_t ao = (uint32_t)((ka + ks * 16) * 2), bo = (uint32_t)((kb + ks * 16) * 2);
                uint32_t b0,b1,b2,b3;
                ldsm4(b0,b1,b2,b3, bAddr + bo);
                #pragma unroll
                for (int mt = 0; mt < 4; mt++) {
                    uint32_t a0,a1,a2,a3;
                    ldsm4(a0,a1,a2,a3, aAddr + mt * 16 * TS4 * 2 + ao);
                    mma16816(acc[mt][0], a0,a1,a2,a3, b0,b1);
                    mma16816(acc[mt][1], a0,a1,a2,a3, b2,b3);
                }
            }
        }
    }

    // epilogue
    int b = bh >> 4, h = bh & 15;
    #pragma unroll
    for (int mt = 0; mt < 4; mt++) {
        int row = wm * 64 + mt * 16 + (lane >> 2);
        int qg  = qt * 128 + row;
        float si0 = g_sinv[bh * 1024 + qg];
        float si8 = g_sinv[bh * 1024 + qg + 8];
        float* O0 = Out + ((size_t)(b * 1024) + qg) * 1024 + h * 64 + wn * 16 + (lane & 3) * 2;
        #pragma unroll
        for (int nt = 0; nt < 2; nt++) {
            *(float2*)(O0 + nt * 8)            = make_float2(acc[mt][nt][0] * si0, acc[mt][nt][1] * si0);
            *(float2*)(O0 + 8 * 1024 + nt * 8) = make_float2(acc[mt][nt][2] * si8, acc[mt][nt][3] * si8);
        }
    }
}

// ---------------- host ----------------
extern "C" void kernel_launch(void* const* d_in, const int* in_sizes, int n_in,
                              void* d_out, int out_size)
{
    const float* Q  = (const float*)d_in[0];
    const float* K  = (const float*)d_in[1];
    const float* V  = (const float*)d_in[2];
    const float* RK = (const float*)d_in[3];
    const float* RV = (const float*)d_in[4];
    float* Out = (float*)d_out;

    __nv_bfloat16 *qd, *kd;
    cudaGetSymbolAddress((void**)&qd, g_Q);
    cudaGetSymbolAddress((void**)&kd, g_K);

    cudaFuncSetAttribute(k_vt,     cudaFuncAttributeMaxDynamicSharedMemorySize, 256*65*4);
    cudaFuncSetAttribute(k_bias,   cudaFuncAttributeMaxDynamicSharedMemorySize, K1_SMEM);
    cudaFuncSetAttribute(k_scores, cudaFuncAttributeMaxDynamicSharedMemorySize, K2_SMEM);
    cudaFuncSetAttribute(k_out,    cudaFuncAttributeMaxDynamicSharedMemorySize, K4_SMEM);

    k_split<<<4096, 256>>>(Q, qd, 1.0f);
    k_split<<<4096, 256>>>(K, kd, 0.125f);
    k_vt<<<dim3(4, BHN), 256, 256*65*4>>>(V);
    k_rel<<<NDP, 64>>>(RK, RV);
    k_bias  <<<dim3(8,  BHN), 256, K1_SMEM>>>();
    k_scores<<<dim3(32, BHN), 256, K2_SMEM>>>();
    k_out   <<<dim3(8,  BHN), 256, K4_SMEM>>>(Out);
}

// round 6
// speedup vs baseline: 2.9329x; 1.2136x over previous
#include <cuda_runtime.h>
#include <cuda_bf16.h>
#include <cstdint>

// CircularRelativePositionAttention — mma.sync bf16 hi/lo split, fully fused attention.
// B=4,H=16 -> 64 head-batches; S=1024; dh=64.
//
//  k_split : Q (x1), K (x1/8) -> bf16 [bh][s][128] (hi 0-63 | lo 64-127)
//  k_vt    : V -> transposed  [bh][e 64][2048]   (hi s 0-1023 | lo 1024-2047)
//  k_rel   : rel_k -> [640][128] (rows>=513 zero); rel_v -> [64][1280] transposed
//  k_bias  : G[bh][q][520] = Q . rel_k^T  (fp32)
//  k_fused : per (bh, 32 q-rows): QK^T (cp.async dbuf) -> smem fp32 scores;
//            stage G to smem; softmax (+G bias) -> P bf16 hi/lo in place;
//            P@V; pooled in place; pooled@RV; out = acc * (1/sum).
//
// Round-6 fix: V chunk-0 prefetch is issued AFTER softmax — G spans both B
// buffers (66560 B) and the round-5 version raced the prefetch against
// softmax reads of G rows 16-31.

#define BHN 64
#define NDP 520

__device__ __align__(16) __nv_bfloat16 g_Q [(size_t)BHN*1024*128];
__device__ __align__(16) __nv_bfloat16 g_K [(size_t)BHN*1024*128];
__device__ __align__(16) __nv_bfloat16 g_Vt[(size_t)BHN*64*2048];
__device__ __align__(16) __nv_bfloat16 g_RK[(size_t)640*128];
__device__ __align__(16) __nv_bfloat16 g_RVt[(size_t)64*1280];
__device__ __align__(16) float         g_G [(size_t)BHN*1024*NDP];

// ---------------- helpers ----------------
__device__ __forceinline__ uint32_t smem_u32(const void* p) {
    uint32_t a;
    asm("{ .reg .u64 t; cvta.to.shared.u64 t, %1; cvt.u32.u64 %0, t; }" : "=r"(a) : "l"(p));
    return a;
}
__device__ __forceinline__ void ldsm4(uint32_t& r0, uint32_t& r1, uint32_t& r2, uint32_t& r3, uint32_t a) {
    asm volatile("ldmatrix.sync.aligned.m8n8.x4.shared.b16 {%0,%1,%2,%3}, [%4];"
                 : "=r"(r0), "=r"(r1), "=r"(r2), "=r"(r3) : "r"(a));
}
__device__ __forceinline__ void mma16816(float* c, uint32_t a0, uint32_t a1, uint32_t a2, uint32_t a3,
                                         uint32_t b0, uint32_t b1) {
    asm volatile("mma.sync.aligned.m16n8k16.row.col.f32.bf16.bf16.f32 "
                 "{%0,%1,%2,%3}, {%4,%5,%6,%7}, {%8,%9}, {%0,%1,%2,%3};"
                 : "+f"(c[0]), "+f"(c[1]), "+f"(c[2]), "+f"(c[3])
                 : "r"(a0), "r"(a1), "r"(a2), "r"(a3), "r"(b0), "r"(b1));
}
__device__ __forceinline__ void split_bf(float x, __nv_bfloat16& h, __nv_bfloat16& l) {
    h = __float2bfloat16(x);
    l = __float2bfloat16(x - __bfloat162float(h));
}
__device__ __forceinline__ uint32_t pack2(__nv_bfloat16 a, __nv_bfloat16 b) {
    __nv_bfloat162 t = {a, b};
    return *(uint32_t*)&t;
}
__device__ __forceinline__ void cpasync16(uint32_t d, const void* s) {
    asm volatile("cp.async.cg.shared.global [%0], [%1], 16;" :: "r"(d), "l"(s));
}
#define CP_COMMIT() asm volatile("cp.async.commit_group;" ::: "memory")
#define CP_WAIT1()  asm volatile("cp.async.wait_group 1;" ::: "memory")
#define CP_WAIT0()  asm volatile("cp.async.wait_group 0;" ::: "memory")

// ---------------- prep kernels ----------------
__global__ void k_split(const float* __restrict__ src, __nv_bfloat16* __restrict__ dst, float scale)
{
    int i4 = blockIdx.x * 256 + threadIdx.x;
    int e4 = (i4 & 15) * 4;
    int s  = (i4 >> 4) & 1023;
    int bh = i4 >> 14;
    int b = bh >> 4, h = bh & 15;
    float4 v = *(const float4*)(src + ((size_t)(b * 1024) + s) * 1024 + h * 64 + e4);
    __nv_bfloat16 h0,l0,h1,l1,h2,l2,h3,l3;
    split_bf(v.x*scale,h0,l0); split_bf(v.y*scale,h1,l1);
    split_bf(v.z*scale,h2,l2); split_bf(v.w*scale,h3,l3);
    __nv_bfloat16* d = dst + ((size_t)bh * 1024 + s) * 128;
    *(uint2*)(d + e4)      = make_uint2(pack2(h0,h1), pack2(h2,h3));
    *(uint2*)(d + 64 + e4) = make_uint2(pack2(l0,l1), pack2(l2,l3));
}

__global__ void k_vt(const float* __restrict__ V)
{
    extern __shared__ float sv[];    // [256][65]
    int tid = threadIdx.x, sc = blockIdx.x, bh = blockIdx.y;
    int b = bh >> 4, h = bh & 15;
    for (int i = tid; i < 4096; i += 256) {
        int s = i >> 4, e4 = (i & 15) * 4;
        float4 v = *(const float4*)(V + ((size_t)(b * 1024) + sc * 256 + s) * 1024 + h * 64 + e4);
        float* d = sv + s * 65 + e4;
        d[0]=v.x; d[1]=v.y; d[2]=v.z; d[3]=v.w;
    }
    __syncthreads();
    for (int i = tid; i < 4096; i += 256) {
        int e = i >> 6, s4 = (i & 63) * 4;
        __nv_bfloat16 hh[4], ll[4];
        #pragma unroll
        for (int j = 0; j < 4; j++) split_bf(sv[(s4 + j) * 65 + e], hh[j], ll[j]);
        size_t di = ((size_t)bh * 64 + e) * 2048 + sc * 256 + s4;
        *(uint2*)(g_Vt + di)        = make_uint2(pack2(hh[0],hh[1]), pack2(hh[2],hh[3]));
        *(uint2*)(g_Vt + di + 1024) = make_uint2(pack2(ll[0],ll[1]), pack2(ll[2],ll[3]));
    }
}

__global__ void k_rel(const float* __restrict__ RK, const float* __restrict__ RV)
{
    int r = blockIdx.x;      // 0..639
    int e = threadIdx.x;     // 0..63
    float fk = 0.f, fv = 0.f;
    if (r < 513) { fk = RK[(size_t)r * 64 + e]; fv = RV[(size_t)r * 64 + e]; }
    __nv_bfloat16 h, l;
    split_bf(fk, h, l);
    g_RK[(size_t)r * 128 + e] = h;  g_RK[(size_t)r * 128 + 64 + e] = l;
    split_bf(fv, h, l);
    g_RVt[(size_t)e * 1280 + r] = h;  g_RVt[(size_t)e * 1280 + 640 + r] = l;
}

// ---------------- K1: G = Q . RK^T  (fp32, stride 520) ----------------
#define TS1 136
#define K1_SMEM (2*128*TS1*2)
__global__ __launch_bounds__(256) void k_bias()
{
    extern __shared__ char smc[];
    __nv_bfloat16* smA = (__nv_bfloat16*)smc;
    __nv_bfloat16* smB = smA + 128 * TS1;
    int tid = threadIdx.x, lane = tid & 31, wid = tid >> 5;
    int qt = blockIdx.x, bh = blockIdx.y;
    int wm = wid & 1, wn = wid >> 1;

    const __nv_bfloat16* Ag = g_Q + ((size_t)bh * 1024 + qt * 128) * 128;
    for (int i = tid; i < 2048; i += 256) {
        int r = i >> 4, c = (i & 15) * 8;
        *(uint4*)(smA + r * TS1 + c) = *(const uint4*)(Ag + r * 128 + c);
    }
    uint32_t aAddr = smem_u32(smA) + (uint32_t)(((wm * 64 + (lane & 15)) * TS1 + ((lane >> 4) << 3)) * 2);
    uint32_t bAddr = smem_u32(smB) + (uint32_t)(((wn * 32 + (lane & 7) + ((lane >> 4) << 3)) * TS1 + ((lane & 8) ? 8 : 0)) * 2);

    for (int nc = 0; nc < 5; nc++) {
        __syncthreads();
        const __nv_bfloat16* Bg = g_RK + (size_t)nc * 128 * 128;
        for (int i = tid; i < 2048; i += 256) {
            int r = i >> 4, c = (i & 15) * 8;
            *(uint4*)(smB + r * TS1 + c) = *(const uint4*)(Bg + r * 128 + c);
        }
        __syncthreads();

        float acc[4][4][4];
        #pragma unroll
        for (int m = 0; m < 4; m++) for (int n = 0; n < 4; n++) for (int i = 0; i < 4; i++) acc[m][n][i] = 0.f;

        #pragma unroll
        for (int p = 0; p < 3; p++) {
            int ka = (p == 1) ? 64 : 0, kb = (p == 2) ? 64 : 0;
            #pragma unroll
            for (int ks = 0; ks < 4; ks++) {
                uint32_t ao = (uint32_t)((ka + ks * 16) * 2), bo = (uint32_t)((kb + ks * 16) * 2);
                uint32_t b0,b1,b2,b3,b4,b5,b6,b7;
                ldsm4(b0,b1,b2,b3, bAddr + bo);
                ldsm4(b4,b5,b6,b7, bAddr + 16 * TS1 * 2 + bo);
                #pragma unroll
                for (int mt = 0; mt < 4; mt++) {
                    uint32_t a0,a1,a2,a3;
                    ldsm4(a0,a1,a2,a3, aAddr + mt * 16 * TS1 * 2 + ao);
                    mma16816(acc[mt][0], a0,a1,a2,a3, b0,b1);
                    mma16816(acc[mt][1], a0,a1,a2,a3, b2,b3);
                    mma16816(acc[mt][2], a0,a1,a2,a3, b4,b5);
                    mma16816(acc[mt][3], a0,a1,a2,a3, b6,b7);
                }
            }
        }
        #pragma unroll
        for (int mt = 0; mt < 4; mt++) {
            int row = wm * 64 + mt * 16 + (lane >> 2);
            float* G0 = g_G + ((size_t)bh * 1024 + qt * 128 + row) * NDP;
            #pragma unroll
            for (int nt = 0; nt < 4; nt++) {
                int col = nc * 128 + wn * 32 + nt * 8 + (lane & 3) * 2;
                if (col < NDP) {
                    *(float2*)(G0 + col)           = make_float2(acc[mt][nt][0], acc[mt][nt][1]);
                    *(float2*)(G0 + 8 * NDP + col) = make_float2(acc[mt][nt][2], acc[mt][nt][3]);
                }
            }
        }
    }
}

// ---------------- fused attention kernel ----------------
#define TSQ 136
#define TSV 264
#define SM_S    0                       // smS / P buffer: 32 rows x 4160 B = 133120
#define SM_B0   133120                  // B tile buf 0: 34816
#define SM_B1   (133120 + 34816)        // B tile buf 1: 34816
#define SM_A    (133120 + 69632)        // Q tile: 8704
#define SM_SINV (SM_A + 8704)           // 128
#define FUSED_SMEM (SM_SINV + 128)

// one A(P or pooled) x B(V or RV) chunk: 3 split passes, K=128
__device__ __forceinline__ void mma_chunk_av(float acc[2][4], const char* smc, int rowP,
                                             int colbase, int csel, uint32_t bPV)
{
    uint32_t aPbase = smem_u32(smc) + (uint32_t)(SM_S + rowP * 4160);
    #pragma unroll
    for (int p = 0; p < 3; p++) {
        int aBase = colbase + ((p == 1) ? 1024 : 0);
        int kb = (p == 2) ? 128 : 0;
        #pragma unroll
        for (int ks = 0; ks < 8; ks++) {
            int cb = (aBase + ks * 16) >> 3;
            uint32_t a0,a1,a2,a3,b0,b1,b2,b3;
            ldsm4(a0,a1,a2,a3, aPbase + (uint32_t)((cb + csel) << 4));
            ldsm4(b0,b1,b2,b3, bPV + (uint32_t)((kb + ks * 16) * 2));
            mma16816(acc[0], a0,a1,a2,a3, b0,b1);
            mma16816(acc[1], a0,a1,a2,a3, b2,b3);
        }
    }
}

__global__ __launch_bounds__(256, 1) void k_fused(float* __restrict__ Out)
{
    extern __shared__ char smc[];
    uint32_t sb = smem_u32(smc);
    int tid = threadIdx.x, lane = tid & 31, wid = tid >> 5;
    int qt = blockIdx.x, bh = blockIdx.y;
    int wm = wid & 1, wn = wid >> 1;
    const int q0 = qt * 32;
    float* smS = (float*)(smc + SM_S);
    float* sinvp = (float*)(smc + SM_SINV);

    // Q tile [32][TSQ]
    const __nv_bfloat16* Qg = g_Q + ((size_t)bh * 1024 + q0) * 128;
    for (int i = tid; i < 512; i += 256) {
        int r = i >> 4, c = (i & 15) * 8;
        *(uint4*)(smc + SM_A + (r * TSQ + c) * 2) = *(const uint4*)(Qg + r * 128 + c);
    }

    const __nv_bfloat16* Kg = g_K + (size_t)bh * 1024 * 128;
    const __nv_bfloat16* Vg = g_Vt + (size_t)bh * 64 * 2048;

    // ---- phase 1: QK^T -> smS fp32 ----
    {
        // prefetch K chunk 0
        for (int i = tid; i < 2048; i += 256) {
            int r = i >> 4, ch = i & 15;
            cpasync16(sb + SM_B0 + (uint32_t)((r * TSQ + ch * 8) * 2), Kg + r * 128 + ch * 8);
        }
        CP_COMMIT();

        uint32_t aQK = sb + SM_A + (uint32_t)(((wm * 16 + (lane & 15)) * TSQ + ((lane >> 4) << 3)) * 2);
        for (int kc = 0; kc < 8; kc++) {
            if (kc + 1 < 8) {
                uint32_t d0 = sb + (((kc + 1) & 1) ? SM_B1 : SM_B0);
                const __nv_bfloat16* src = Kg + (size_t)(kc + 1) * 128 * 128;
                for (int i = tid; i < 2048; i += 256) {
                    int r = i >> 4, ch = i & 15;
                    cpasync16(d0 + (uint32_t)((r * TSQ + ch * 8) * 2), src + r * 128 + ch * 8);
                }
                CP_COMMIT(); CP_WAIT1();
            } else CP_WAIT0();
            __syncthreads();

            uint32_t bB = sb + ((kc & 1) ? SM_B1 : SM_B0);
            uint32_t bQK = bB + (uint32_t)(((wn * 32 + (lane & 7) + ((lane >> 4) << 3)) * TSQ + ((lane & 8) ? 8 : 0)) * 2);
            float acc[4][4];
            #pragma unroll
            for (int n = 0; n < 4; n++) for (int i = 0; i < 4; i++) acc[n][i] = 0.f;
            #pragma unroll
            for (int p = 0; p < 3; p++) {
                int ka = (p == 1) ? 64 : 0, kb = (p == 2) ? 64 : 0;
                #pragma unroll
                for (int ks = 0; ks < 4; ks++) {
                    uint32_t ao = (uint32_t)((ka + ks * 16) * 2), bo = (uint32_t)((kb + ks * 16) * 2);
                    uint32_t b0,b1,b2,b3,b4,b5,b6,b7, a0,a1,a2,a3;
                    ldsm4(b0,b1,b2,b3, bQK + bo);
                    ldsm4(b4,b5,b6,b7, bQK + 16 * TSQ * 2 + bo);
                    ldsm4(a0,a1,a2,a3, aQK + ao);
                    mma16816(acc[0], a0,a1,a2,a3, b0,b1);
                    mma16816(acc[1], a0,a1,a2,a3, b2,b3);
                    mma16816(acc[2], a0,a1,a2,a3, b4,b5);
                    mma16816(acc[3], a0,a1,a2,a3, b6,b7);
                }
            }
            int r0 = wm * 16 + (lane >> 2);
            #pragma unroll
            for (int nt = 0; nt < 4; nt++) {
                int kg = kc * 128 + wn * 32 + nt * 8 + (lane & 3) * 2;
                *(float2*)(smS + r0 * 1040 + kg)       = make_float2(acc[nt][0], acc[nt][1]);
                *(float2*)(smS + (r0 + 8) * 1040 + kg) = make_float2(acc[nt][2], acc[nt][3]);
            }
            __syncthreads();
        }
    }

    // ---- phase 2: stage G [32][520] into B buffers (spans B0+B1) ----
    {
        const float* Gg = g_G + ((size_t)bh * 1024 + q0) * NDP;
        for (int i = tid; i < 4160; i += 256)
            cpasync16(sb + SM_B0 + (uint32_t)(i * 16), (const char*)Gg + i * 16);
        CP_COMMIT(); CP_WAIT0();
    }
    __syncthreads();

    // ---- phase 3: softmax (+bias) -> P bf16 hi/lo in place ----
    {
        const float* smG = (const float*)(smc + SM_B0);
        for (int it = 0; it < 4; it++) {
            int r = it * 8 + wid;
            int qg = q0 + r;
            const float* row = smS + r * 1040;
            float4 f[8];
            float m = -1e30f;
            #pragma unroll
            for (int j = 0; j < 8; j++) {
                f[j] = ((const float4*)row)[lane + 32 * j];
                int k0 = (lane + 32 * j) * 4;
                #pragma unroll
                for (int e = 0; e < 4; e++) {
                    int d = (qg - (k0 + e)) & 1023;
                    int dist = min(d, 1024 - d);
                    (&f[j].x)[e] += smG[r * 520 + dist];
                }
                m = fmaxf(m, fmaxf(fmaxf(f[j].x, f[j].y), fmaxf(f[j].z, f[j].w)));
            }
            #pragma unroll
            for (int o = 16; o; o >>= 1) m = fmaxf(m, __shfl_xor_sync(0xFFFFFFFFu, m, o));
            float sum = 0.f;
            char* rbase = smc + SM_S + r * 4160;
            #pragma unroll
            for (int j = 0; j < 8; j++) {
                float p0 = __expf(f[j].x - m), p1 = __expf(f[j].y - m);
                float p2 = __expf(f[j].z - m), p3 = __expf(f[j].w - m);
                sum += (p0 + p1) + (p2 + p3);
                __nv_bfloat16 h0,l0,h1,l1,h2,l2,h3,l3;
                split_bf(p0,h0,l0); split_bf(p1,h1,l1); split_bf(p2,h2,l2); split_bf(p3,h3,l3);
                int k4 = (lane + 32 * j) * 4;
                *(uint2*)(rbase + 2 * k4)        = make_uint2(pack2(h0,h1), pack2(h2,h3));
                *(uint2*)(rbase + 2048 + 2 * k4) = make_uint2(pack2(l0,l1), pack2(l2,l3));
            }
            #pragma unroll
            for (int o = 16; o; o >>= 1) sum += __shfl_xor_sync(0xFFFFFFFFu, sum, o);
            if (lane == 0) sinvp[r] = 1.f / sum;
        }
    }
    __syncthreads();   // all G reads + P writes complete before reusing B buffers

    // prefetch V chunk 0 into buf1 (G fully consumed now)
    for (int i = tid; i < 2048; i += 256) {
        int r = i >> 5, ch = i & 31;
        const __nv_bfloat16* s = Vg + r * 2048 + ((ch < 16) ? (ch * 8) : (1024 + (ch - 16) * 8));
        cpasync16(sb + SM_B1 + (uint32_t)((r * TSV + ch * 8) * 2), s);
    }
    CP_COMMIT();

    // ---- phase 4: P@V (8 chunks) then pooled@RV (5 chunks) ----
    float acc[2][4];
    #pragma unroll
    for (int n = 0; n < 2; n++) for (int i = 0; i < 4; i++) acc[n][i] = 0.f;
    const int rowP = wm * 16 + (lane & 15);
    const int csel = lane >> 4;

    for (int c = 0; c < 13; c++) {
        if (c + 1 < 13) {
            uint32_t d0 = sb + ((((c + 1) & 1) ^ 1) ? SM_B1 : SM_B0);
            if (c + 1 < 8) {
                const __nv_bfloat16* base = Vg;
                int cc = c + 1;
                for (int i = tid; i < 2048; i += 256) {
                    int r = i >> 5, ch = i & 31;
                    const __nv_bfloat16* s = base + r * 2048 +
                        ((ch < 16) ? (cc * 128 + ch * 8) : (1024 + cc * 128 + (ch - 16) * 8));
                    cpasync16(d0 + (uint32_t)((r * TSV + ch * 8) * 2), s);
                }
            } else {
                int cc = c + 1 - 8;
                for (int i = tid; i < 2048; i += 256) {
                    int r = i >> 5, ch = i & 31;
                    const __nv_bfloat16* s = g_RVt + r * 1280 +
                        ((ch < 16) ? (cc * 128 + ch * 8) : (640 + cc * 128 + (ch - 16) * 8));
                    cpasync16(d0 + (uint32_t)((r * TSV + ch * 8) * 2), s);
                }
            }
            CP_COMMIT(); CP_WAIT1();
        } else CP_WAIT0();
        __syncthreads();

        uint32_t bB = sb + (((c & 1) ^ 1) ? SM_B1 : SM_B0);
        uint32_t bPV = bB + (uint32_t)(((wn * 16 + (lane & 7) + ((lane >> 4) << 3)) * TSV + ((lane & 8) ? 8 : 0)) * 2);
        mma_chunk_av(acc, smc, rowP, ((c < 8) ? c : c - 8) * 128, csel, bPV);

        if (c == 7) {
            // pooled: overwrite P cols 0..639 (hi) / 1024..1663 (lo), warp per row
            __syncthreads();
            for (int it = 0; it < 4; it++) {
                int r = it * 8 + wid, qg = q0 + r;
                char* rbase = smc + SM_S + r * 4160;
                float pv[20];
                #pragma unroll
                for (int t2 = 0; t2 < 20; t2++) {
                    int d = lane + t2 * 32;
                    float v = 0.f;
                    if (d <= 512) {
                        int k1 = (qg + d) & 1023;
                        v = __bfloat162float(*(const __nv_bfloat16*)(rbase + 2 * k1))
                          + __bfloat162float(*(const __nv_bfloat16*)(rbase + 2048 + 2 * k1));
                        if (d != 0 && d != 512) {
                            int k2 = (qg - d) & 1023;
                            v += __bfloat162float(*(const __nv_bfloat16*)(rbase + 2 * k2))
                               + __bfloat162float(*(const __nv_bfloat16*)(rbase + 2048 + 2 * k2));
                        }
                    }
                    pv[t2] = v;
                }
                __syncwarp();
                #pragma unroll
                for (int t2 = 0; t2 < 20; t2++) {
                    int d = lane + t2 * 32;
                    __nv_bfloat16 h, l;
                    split_bf(pv[t2], h, l);
                    *(__nv_bfloat16*)(rbase + 2 * d) = h;
                    *(__nv_bfloat16*)(rbase + 2048 + 2 * d) = l;
                }
            }
        }
        __syncthreads();
    }

    // ---- epilogue ----
    {
        int r0 = wm * 16 + (lane >> 2);
        float si0 = sinvp[r0], si8 = sinvp[r0 + 8];
        int b = bh >> 4, h = bh & 15;
        float* O0 = Out + ((size_t)(b * 1024) + q0 + r0) * 1024 + h * 64 + wn * 16 + (lane & 3) * 2;
        #pragma unroll
        for (int nt = 0; nt < 2; nt++) {
            *(float2*)(O0 + nt * 8)            = make_float2(acc[nt][0] * si0, acc[nt][1] * si0);
            *(float2*)(O0 + 8 * 1024 + nt * 8) = make_float2(acc[nt][2] * si8, acc[nt][3] * si8);
        }
    }
}

// ---------------- host ----------------
extern "C" void kernel_launch(void* const* d_in, const int* in_sizes, int n_in,
                              void* d_out, int out_size)
{
    const float* Q  = (const float*)d_in[0];
    const float* K  = (const float*)d_in[1];
    const float* V  = (const float*)d_in[2];
    const float* RK = (const float*)d_in[3];
    const float* RV = (const float*)d_in[4];
    float* Out = (float*)d_out;

    __nv_bfloat16 *qd, *kd;
    cudaGetSymbolAddress((void**)&qd, g_Q);
    cudaGetSymbolAddress((void**)&kd, g_K);

    cudaFuncSetAttribute(k_vt,    cudaFuncAttributeMaxDynamicSharedMemorySize, 256*65*4);
    cudaFuncSetAttribute(k_bias,  cudaFuncAttributeMaxDynamicSharedMemorySize, K1_SMEM);
    cudaFuncSetAttribute(k_fused, cudaFuncAttributeMaxDynamicSharedMemorySize, FUSED_SMEM);

    k_split<<<4096, 256>>>(Q, qd, 1.0f);
    k_split<<<4096, 256>>>(K, kd, 0.125f);
    k_vt<<<dim3(4, BHN), 256, 256*65*4>>>(V);
    k_rel<<<640, 64>>>(RK, RV);
    k_bias <<<dim3(8,  BHN), 256, K1_SMEM>>>();
    k_fused<<<dim3(32, BHN), 256, FUSED_SMEM>>>(Out);
}